// round 2
// baseline (speedup 1.0000x reference)
#include <cuda_runtime.h>
#include <cuda_bf16.h>
#include <math.h>

// Problem constants (match reference)
#define HID 128
#define TILE 128          // edges per CTA
#define PAD 132           // padded row stride for h (floats)
#define IN_SZ 9
#define FPAD 12           // padded feature row
#define NTHREADS 256

// Shared memory layout (dynamic):
//   h     : TILE * PAD floats          (67584 B)
//   feats : TILE * FPAD floats         ( 6144 B)
//   wb4   : 256 floats (w4 staged)     ( 1024 B)
//   sdst  : TILE ints                  (  512 B)
#define SMEM_H_FLOATS    (TILE * PAD)
#define SMEM_F_FLOATS    (TILE * FPAD)
#define SMEM_W4_FLOATS   (256)
#define SMEM_TOTAL_BYTES ((SMEM_H_FLOATS + SMEM_F_FLOATS + SMEM_W4_FLOATS) * 4 + TILE * 4)

__global__ void zero_kernel(float* __restrict__ out, int n) {
    int i = blockIdx.x * blockDim.x + threadIdx.x;
    if (i < n) out[i] = 0.0f;
}

__global__ __launch_bounds__(NTHREADS, 2)
void gnn_edge_mlp_kernel(
    const float* __restrict__ pos,
    const float* __restrict__ vel,
    const float* __restrict__ a,
    const float* __restrict__ vnorm,
    const float* __restrict__ w0, const float* __restrict__ b0,
    const float* __restrict__ w1, const float* __restrict__ b1,
    const float* __restrict__ w2, const float* __restrict__ b2,
    const float* __restrict__ w3, const float* __restrict__ b3,
    const float* __restrict__ w4, const float* __restrict__ b4,
    const int* __restrict__ ei,          // int32! (JAX x64 disabled downgrades int64)
    const int* __restrict__ data_id_p,
    float* __restrict__ out,
    int E, int N)
{
    extern __shared__ float smem[];
    float* h     = smem;                                   // [TILE][PAD]
    float* feats = smem + SMEM_H_FLOATS;                   // [TILE][FPAD]
    float* wb4   = smem + SMEM_H_FLOATS + SMEM_F_FLOATS;   // [256]
    int*   sdst  = (int*)(wb4 + SMEM_W4_FLOATS);           // [TILE]

    const int tid = threadIdx.x;
    const int e0  = blockIdx.x * TILE;

    // Stage w4 (128x2) into shared
    wb4[tid] = w4[tid];

    // ---- Feature build: threads 0..127, one edge each ----
    if (tid < TILE) {
        int e = e0 + tid;
        if (e < E) {
            int dst = ei[e];            // row 0 of [2, E]
            int src = ei[E + e];        // row 1 of [2, E]
            sdst[tid] = dst;
            float inv_vn = 1.0f / vnorm[0];
            float dpx = (pos[2 * src]     - pos[2 * dst])     * 10.0f;  // / MAX_RADIUS (0.1)
            float dpy = (pos[2 * src + 1] - pos[2 * dst + 1]) * 10.0f;
            float r = sqrtf(dpx * dpx + dpy * dpy);
            int did = *data_id_p;  // value 1; low 32 bits correct for i32 or i64 (LE)
            const float* emb = a + ((size_t)did * N + dst) * 2;
            float* f = feats + tid * FPAD;
            f[0] = dpx;
            f[1] = dpy;
            f[2] = r;
            f[3] = vel[2 * dst]     * inv_vn;
            f[4] = vel[2 * dst + 1] * inv_vn;
            f[5] = vel[2 * src]     * inv_vn;
            f[6] = vel[2 * src + 1] * inv_vn;
            f[7] = emb[0];
            f[8] = emb[1];
        } else {
            sdst[tid] = -1;
            float* f = feats + tid * FPAD;
            #pragma unroll
            for (int j = 0; j < IN_SZ; j++) f[j] = 0.0f;
        }
    }
    __syncthreads();

    // Thread tiling for the GEMM layers:
    //   cg = tid & 31  -> output columns [4*cg, 4*cg+3]
    //   rg = tid >> 5  -> output rows    [16*rg, 16*rg+15]
    // Each warp is one rg -> all 32 lanes read the same h[row][k] (LDS broadcast).
    const int cg = tid & 31;
    const int rg = tid >> 5;
    const int row0 = rg * 16;
    const int col0 = cg * 4;

    float acc[16][4];

    // ---- Layer 0: feats[128x9] @ w0[9x128] + b0, ReLU ----
    {
        float4 bb = *(const float4*)(b0 + col0);
        #pragma unroll
        for (int i = 0; i < 16; i++) {
            acc[i][0] = bb.x; acc[i][1] = bb.y; acc[i][2] = bb.z; acc[i][3] = bb.w;
        }
        #pragma unroll
        for (int k = 0; k < IN_SZ; k++) {
            float4 w = *(const float4*)(w0 + k * HID + col0);
            #pragma unroll
            for (int i = 0; i < 16; i++) {
                float x = feats[(row0 + i) * FPAD + k];
                acc[i][0] = fmaf(x, w.x, acc[i][0]);
                acc[i][1] = fmaf(x, w.y, acc[i][1]);
                acc[i][2] = fmaf(x, w.z, acc[i][2]);
                acc[i][3] = fmaf(x, w.w, acc[i][3]);
            }
        }
        #pragma unroll
        for (int i = 0; i < 16; i++) {
            float4 v;
            v.x = fmaxf(acc[i][0], 0.0f);
            v.y = fmaxf(acc[i][1], 0.0f);
            v.z = fmaxf(acc[i][2], 0.0f);
            v.w = fmaxf(acc[i][3], 0.0f);
            *(float4*)&h[(row0 + i) * PAD + col0] = v;
        }
    }
    __syncthreads();

    // ---- Layers 1..3: h[128x128] @ w[128x128] + b, ReLU (in-place ping via 2 syncs) ----
    const float* Ws[3] = { w1, w2, w3 };
    const float* Bs[3] = { b1, b2, b3 };
    for (int L = 0; L < 3; L++) {
        const float* W = Ws[L];
        float4 bb = *(const float4*)(Bs[L] + col0);
        #pragma unroll
        for (int i = 0; i < 16; i++) {
            acc[i][0] = bb.x; acc[i][1] = bb.y; acc[i][2] = bb.z; acc[i][3] = bb.w;
        }
        #pragma unroll 4
        for (int k = 0; k < HID; k++) {
            float4 w = *(const float4*)(W + k * HID + col0);
            #pragma unroll
            for (int i = 0; i < 16; i++) {
                float x = h[(row0 + i) * PAD + k];   // warp-broadcast LDS
                acc[i][0] = fmaf(x, w.x, acc[i][0]);
                acc[i][1] = fmaf(x, w.y, acc[i][1]);
                acc[i][2] = fmaf(x, w.z, acc[i][2]);
                acc[i][3] = fmaf(x, w.w, acc[i][3]);
            }
        }
        __syncthreads();   // all reads of h done before overwrite
        #pragma unroll
        for (int i = 0; i < 16; i++) {
            float4 v;
            v.x = fmaxf(acc[i][0], 0.0f);
            v.y = fmaxf(acc[i][1], 0.0f);
            v.z = fmaxf(acc[i][2], 0.0f);
            v.w = fmaxf(acc[i][3], 0.0f);
            *(float4*)&h[(row0 + i) * PAD + col0] = v;
        }
        __syncthreads();
    }

    // ---- Layer 4: h[128x128] @ w4[128x2] + b4, scatter-add ----
    if (tid < TILE) {
        float m0 = b4[0];
        float m1 = b4[1];
        const float* hr = h + tid * PAD;
        #pragma unroll 8
        for (int k = 0; k < HID; k++) {
            float x = hr[k];
            m0 = fmaf(x, wb4[2 * k],     m0);
            m1 = fmaf(x, wb4[2 * k + 1], m1);
        }
        int dst = sdst[tid];
        if (dst >= 0) {
            atomicAdd(&out[2 * dst],     m0);
            atomicAdd(&out[2 * dst + 1], m1);
        }
    }
}

extern "C" void kernel_launch(void* const* d_in, const int* in_sizes, int n_in,
                              void* d_out, int out_size) {
    const float* pos   = (const float*)d_in[0];
    const float* vel   = (const float*)d_in[1];
    const float* a     = (const float*)d_in[2];
    const float* vnorm = (const float*)d_in[3];
    const float* w0    = (const float*)d_in[4];
    const float* b0    = (const float*)d_in[5];
    const float* w1    = (const float*)d_in[6];
    const float* b1    = (const float*)d_in[7];
    const float* w2    = (const float*)d_in[8];
    const float* b2    = (const float*)d_in[9];
    const float* w3    = (const float*)d_in[10];
    const float* b3    = (const float*)d_in[11];
    const float* w4    = (const float*)d_in[12];
    const float* b4    = (const float*)d_in[13];
    const int*   ei    = (const int*)d_in[14];    // int32 [2, E]
    const int*   did   = (const int*)d_in[15];
    float*       out   = (float*)d_out;

    int E = in_sizes[14] / 2;   // edge_index is [2, E]
    int N = in_sizes[0] / 2;    // pos is [N, 2]

    cudaFuncSetAttribute(gnn_edge_mlp_kernel,
                         cudaFuncAttributeMaxDynamicSharedMemorySize,
                         SMEM_TOTAL_BYTES);

    zero_kernel<<<(out_size + 255) / 256, 256>>>(out, out_size);

    int tiles = (E + TILE - 1) / TILE;
    gnn_edge_mlp_kernel<<<tiles, NTHREADS, SMEM_TOTAL_BYTES>>>(
        pos, vel, a, vnorm,
        w0, b0, w1, b1, w2, b2, w3, b3, w4, b4,
        ei, did, out, E, N);
}

// round 4
// speedup vs baseline: 1.8787x; 1.8787x over previous
#include <cuda_runtime.h>
#include <cuda_bf16.h>
#include <math.h>
#include <stdint.h>

#define HID 128
#define TILE 128           // edges per CTA
#define NTHREADS 256       // 8 warps x 16 edges
#define IN_SZ 9
#define H0S 136            // h0 smem row stride (floats), conflict-free frag reads
#define SMEM_BYTES (TILE * H0S * 4 + TILE * 4)

// Pre-packed weight fragments for w1..w3:
// g_wb[L][q][j][lane] = uint4 {bhi_r0, bhi_r1, blo_r0, blo_r1}
// (m16n8k16 B-frag: r0 -> k = 16q + 2t + {0,1}, r1 -> k = 16q + 2t + 8 + {0,1}, n = 8j + g)
__device__ uint4 g_wb[3 * 8 * 16 * 32];

__device__ __forceinline__ void split2(float v0, float v1, uint32_t& hi, uint32_t& lo) {
    __nv_bfloat16 h0 = __float2bfloat16_rn(v0);
    __nv_bfloat16 h1 = __float2bfloat16_rn(v1);
    float r0 = v0 - __bfloat162float(h0);
    float r1 = v1 - __bfloat162float(h1);
    hi = (uint32_t)__bfloat16_as_ushort(h0) | ((uint32_t)__bfloat16_as_ushort(h1) << 16);
    lo = (uint32_t)__bfloat16_as_ushort(__float2bfloat16_rn(r0))
       | ((uint32_t)__bfloat16_as_ushort(__float2bfloat16_rn(r1)) << 16);
}

__device__ __forceinline__ void mma16816(float* d,
                                         uint32_t a0, uint32_t a1, uint32_t a2, uint32_t a3,
                                         uint32_t b0, uint32_t b1) {
    asm volatile(
        "mma.sync.aligned.m16n8k16.row.col.f32.bf16.bf16.f32 "
        "{%0,%1,%2,%3}, {%4,%5,%6,%7}, {%8,%9}, {%0,%1,%2,%3};"
        : "+f"(d[0]), "+f"(d[1]), "+f"(d[2]), "+f"(d[3])
        : "r"(a0), "r"(a1), "r"(a2), "r"(a3), "r"(b0), "r"(b1));
}

// ---------------- prep: pack w1..w3 into mma B-fragment layout ----------------
__global__ void prep_kernel(const float* __restrict__ w1,
                            const float* __restrict__ w2,
                            const float* __restrict__ w3) {
    int s = blockIdx.x * blockDim.x + threadIdx.x;
    if (s >= 3 * 8 * 16 * 32) return;
    int lane = s & 31;
    int j    = (s >> 5) & 15;
    int q    = (s >> 9) & 7;
    int L    = s >> 12;
    int g = lane >> 2, t = lane & 3;
    int n  = j * 8 + g;
    int k0 = q * 16 + t * 2;
    const float* W = (L == 0) ? w1 : (L == 1) ? w2 : w3;
    float v00 = W[k0 * HID + n];
    float v01 = W[(k0 + 1) * HID + n];
    float v10 = W[(k0 + 8) * HID + n];
    float v11 = W[(k0 + 9) * HID + n];
    uint4 o;
    split2(v00, v01, o.x, o.z);
    split2(v10, v11, o.y, o.w);
    g_wb[s] = o;
}

__global__ void zero_kernel(float* __restrict__ out, int n) {
    int i = blockIdx.x * blockDim.x + threadIdx.x;
    if (i < n) out[i] = 0.0f;
}

// ---------------- main kernel ----------------
__global__ __launch_bounds__(NTHREADS)
void gnn_mma_kernel(
    const float* __restrict__ pos,
    const float* __restrict__ vel,
    const float* __restrict__ a,
    const float* __restrict__ vnorm,
    const float* __restrict__ w0, const float* __restrict__ b0,
    const float* __restrict__ b1, const float* __restrict__ b2, const float* __restrict__ b3,
    const float* __restrict__ w4, const float* __restrict__ b4,
    const int* __restrict__ ei,
    const int* __restrict__ data_id_p,
    float* __restrict__ out,
    int E, int N)
{
    extern __shared__ float sm[];
    float* h0s  = sm;                        // [128][H0S]
    int*   sdst = (int*)(sm + TILE * H0S);   // [128]

    const int tid  = threadIdx.x;
    const int warp = tid >> 5;
    const int lane = tid & 31;
    const int g = lane >> 2, t = lane & 3;

    // ---- layer 0 (SIMT fp32): 2 threads per edge, 64 cols each ----
    {
        int e_loc = tid >> 1;
        int cb    = (tid & 1) * 64;
        int e     = blockIdx.x * TILE + e_loc;
        float f[IN_SZ];
        int dstv = -1;
        if (e < E) {
            dstv    = ei[e];
            int src = ei[E + e];
            float inv_vn = 1.0f / vnorm[0];
            float dpx = (pos[2 * src]     - pos[2 * dstv])     * 10.0f;  // / MAX_RADIUS
            float dpy = (pos[2 * src + 1] - pos[2 * dstv + 1]) * 10.0f;
            f[0] = dpx; f[1] = dpy;
            f[2] = sqrtf(dpx * dpx + dpy * dpy);
            f[3] = vel[2 * dstv]     * inv_vn;
            f[4] = vel[2 * dstv + 1] * inv_vn;
            f[5] = vel[2 * src]      * inv_vn;
            f[6] = vel[2 * src + 1]  * inv_vn;
            int did = *data_id_p;
            const float* emb = a + ((size_t)did * N + dstv) * 2;
            f[7] = emb[0]; f[8] = emb[1];
        } else {
            #pragma unroll
            for (int k = 0; k < IN_SZ; k++) f[k] = 0.0f;
        }
        if ((tid & 1) == 0) sdst[e_loc] = dstv;

        float* hr = h0s + e_loc * H0S;
        #pragma unroll
        for (int c0 = 0; c0 < 64; c0 += 32) {
            #pragma unroll
            for (int jj = 0; jj < 32; jj += 4) {
                int c = cb + c0 + jj;
                float4 acc = *(const float4*)(b0 + c);
                #pragma unroll
                for (int k = 0; k < IN_SZ; k++) {
                    float4 w = *(const float4*)(w0 + k * HID + c);
                    acc.x = fmaf(f[k], w.x, acc.x);
                    acc.y = fmaf(f[k], w.y, acc.y);
                    acc.z = fmaf(f[k], w.z, acc.z);
                    acc.w = fmaf(f[k], w.w, acc.w);
                }
                float4 v;
                v.x = fmaxf(acc.x, 0.0f);
                v.y = fmaxf(acc.y, 0.0f);
                v.z = fmaxf(acc.z, 0.0f);
                v.w = fmaxf(acc.w, 0.0f);
                *(float4*)(hr + c) = v;
            }
        }
    }
    __syncthreads();

    // ---- build layer-1 A fragments from h0 (warp-local rows) ----
    uint32_t Ahi[8][4], Alo[8][4];
    {
        const float* r0p = h0s + (warp * 16 + g)     * H0S;
        const float* r1p = h0s + (warp * 16 + g + 8) * H0S;
        #pragma unroll
        for (int q = 0; q < 8; q++) {
            int c = 16 * q + 2 * t;
            float2 p0 = *(const float2*)(r0p + c);
            float2 p1 = *(const float2*)(r1p + c);
            float2 p2 = *(const float2*)(r0p + c + 8);
            float2 p3 = *(const float2*)(r1p + c + 8);
            split2(p0.x, p0.y, Ahi[q][0], Alo[q][0]);
            split2(p1.x, p1.y, Ahi[q][1], Alo[q][1]);
            split2(p2.x, p2.y, Ahi[q][2], Alo[q][2]);
            split2(p3.x, p3.y, Ahi[q][3], Alo[q][3]);
        }
    }

    // ---- hidden layers 1 and 2 (w1, w2): mma + in-register epilogue ----
    for (int L = 0; L < 2; L++) {
        float D[16][4];
        #pragma unroll
        for (int j = 0; j < 16; j++) {
            D[j][0] = 0.f; D[j][1] = 0.f; D[j][2] = 0.f; D[j][3] = 0.f;
        }
        const uint4* wbL = g_wb + (size_t)L * (8 * 16 * 32);
        #pragma unroll
        for (int q = 0; q < 8; q++) {
            #pragma unroll
            for (int j = 0; j < 16; j++) {
                uint4 B = wbL[(q * 16 + j) * 32 + lane];
                mma16816(D[j], Ahi[q][0], Ahi[q][1], Ahi[q][2], Ahi[q][3], B.x, B.y);
                mma16816(D[j], Ahi[q][0], Ahi[q][1], Ahi[q][2], Ahi[q][3], B.z, B.w);
                mma16816(D[j], Alo[q][0], Alo[q][1], Alo[q][2], Alo[q][3], B.x, B.y);
            }
        }
        const float* bL = (L == 0) ? b1 : b2;
        #pragma unroll
        for (int q = 0; q < 8; q++) {
            int j0 = 2 * q, j1 = 2 * q + 1;
            float2 bj0 = *(const float2*)(bL + j0 * 8 + t * 2);
            float2 bj1 = *(const float2*)(bL + j1 * 8 + t * 2);
            float v0 = fmaxf(D[j0][0] + bj0.x, 0.f);
            float v1 = fmaxf(D[j0][1] + bj0.y, 0.f);
            float v2 = fmaxf(D[j0][2] + bj0.x, 0.f);
            float v3 = fmaxf(D[j0][3] + bj0.y, 0.f);
            split2(v0, v1, Ahi[q][0], Alo[q][0]);
            split2(v2, v3, Ahi[q][1], Alo[q][1]);
            float u0 = fmaxf(D[j1][0] + bj1.x, 0.f);
            float u1 = fmaxf(D[j1][1] + bj1.y, 0.f);
            float u2 = fmaxf(D[j1][2] + bj1.x, 0.f);
            float u3 = fmaxf(D[j1][3] + bj1.y, 0.f);
            split2(u0, u1, Ahi[q][2], Alo[q][2]);
            split2(u2, u3, Ahi[q][3], Alo[q][3]);
        }
    }

    // ---- layer 3 (w3) + fused layer 4 (w4) + scatter ----
    {
        float D[16][4];
        #pragma unroll
        for (int j = 0; j < 16; j++) {
            D[j][0] = 0.f; D[j][1] = 0.f; D[j][2] = 0.f; D[j][3] = 0.f;
        }
        const uint4* wbL = g_wb + (size_t)2 * (8 * 16 * 32);
        #pragma unroll
        for (int q = 0; q < 8; q++) {
            #pragma unroll
            for (int j = 0; j < 16; j++) {
                uint4 B = wbL[(q * 16 + j) * 32 + lane];
                mma16816(D[j], Ahi[q][0], Ahi[q][1], Ahi[q][2], Ahi[q][3], B.x, B.y);
                mma16816(D[j], Ahi[q][0], Ahi[q][1], Ahi[q][2], Ahi[q][3], B.z, B.w);
                mma16816(D[j], Alo[q][0], Alo[q][1], Alo[q][2], Alo[q][3], B.x, B.y);
            }
        }
        float m0g = 0.f, m1g = 0.f, m0h = 0.f, m1h = 0.f;
        #pragma unroll
        for (int j = 0; j < 16; j++) {
            float2 bj = *(const float2*)(b3 + j * 8 + t * 2);
            float v0 = fmaxf(D[j][0] + bj.x, 0.f);
            float v1 = fmaxf(D[j][1] + bj.y, 0.f);
            float v2 = fmaxf(D[j][2] + bj.x, 0.f);
            float v3 = fmaxf(D[j][3] + bj.y, 0.f);
            float4 w4v = *(const float4*)(w4 + 2 * (j * 8 + t * 2));  // w4[2k..2k+3]
            m0g = fmaf(v0, w4v.x, fmaf(v1, w4v.z, m0g));
            m1g = fmaf(v0, w4v.y, fmaf(v1, w4v.w, m1g));
            m0h = fmaf(v2, w4v.x, fmaf(v3, w4v.z, m0h));
            m1h = fmaf(v2, w4v.y, fmaf(v3, w4v.w, m1h));
        }
        // reduce across the quad (t = 0..3)
        #pragma unroll
        for (int d = 1; d <= 2; d <<= 1) {
            m0g += __shfl_xor_sync(0xFFFFFFFFu, m0g, d);
            m1g += __shfl_xor_sync(0xFFFFFFFFu, m1g, d);
            m0h += __shfl_xor_sync(0xFFFFFFFFu, m0h, d);
            m1h += __shfl_xor_sync(0xFFFFFFFFu, m1h, d);
        }
        if (t == 0) {
            float bb0 = b4[0], bb1 = b4[1];
            int d0 = sdst[warp * 16 + g];
            if (d0 >= 0) {
                atomicAdd(&out[2 * d0],     m0g + bb0);
                atomicAdd(&out[2 * d0 + 1], m1g + bb1);
            }
            int d1 = sdst[warp * 16 + g + 8];
            if (d1 >= 0) {
                atomicAdd(&out[2 * d1],     m0h + bb0);
                atomicAdd(&out[2 * d1 + 1], m1h + bb1);
            }
        }
    }
}

extern "C" void kernel_launch(void* const* d_in, const int* in_sizes, int n_in,
                              void* d_out, int out_size) {
    const float* pos   = (const float*)d_in[0];
    const float* vel   = (const float*)d_in[1];
    const float* a     = (const float*)d_in[2];
    const float* vnorm = (const float*)d_in[3];
    const float* w0    = (const float*)d_in[4];
    const float* b0    = (const float*)d_in[5];
    const float* w1    = (const float*)d_in[6];
    const float* b1    = (const float*)d_in[7];
    const float* w2    = (const float*)d_in[8];
    const float* b2    = (const float*)d_in[9];
    const float* w3    = (const float*)d_in[10];
    const float* b3    = (const float*)d_in[11];
    const float* w4    = (const float*)d_in[12];
    const float* b4    = (const float*)d_in[13];
    const int*   ei    = (const int*)d_in[14];    // int32 [2, E]
    const int*   did   = (const int*)d_in[15];
    float*       out   = (float*)d_out;

    int E = in_sizes[14] / 2;
    int N = in_sizes[0] / 2;

    cudaFuncSetAttribute(gnn_mma_kernel,
                         cudaFuncAttributeMaxDynamicSharedMemorySize, SMEM_BYTES);

    prep_kernel<<<(3 * 8 * 16 * 32 + 255) / 256, 256>>>(w1, w2, w3);
    zero_kernel<<<(out_size + 255) / 256, 256>>>(out, out_size);

    int tiles = (E + TILE - 1) / TILE;
    gnn_mma_kernel<<<tiles, NTHREADS, SMEM_BYTES>>>(
        pos, vel, a, vnorm, w0, b0, b1, b2, b3, w4, b4,
        ei, did, out, E, N);
}